// round 9
// baseline (speedup 1.0000x reference)
#include <cuda_runtime.h>
#include <math.h>

// Problem constants: z_e [32,64,32,32] f32, emb [1024,64] f32
// Output (concatenated f32): z_st [32,64,32,32] (2097152) | loss (1) | perplexity (1) | encodings [32768,1024] (33554432)
#define NPTS   32768
#define DDIM   64
#define KCODES 1024
#define HWSZ   1024          // H*W
#define OFF_LOSS 2097152
#define OFF_PERP 2097153
#define OFF_ENC  2097154     // NOTE: byte offset 8 mod 16 -> encodings region is only 8B-aligned
#define TK 128               // codes per shared tile

__device__ float g_enorm[KCODES];
__device__ int   g_idx[NPTS];
__device__ float g_losspart[256];

// Kernel A: ||e_k||^2 with sequential in-order FMA (match reference rounding)
__global__ void vq_enorm(const float* __restrict__ emb) {
    int k = blockIdx.x * 128 + threadIdx.x;
    if (k < KCODES) {
        const float* e = emb + (size_t)k * DDIM;
        float s = 0.f;
        #pragma unroll
        for (int d = 0; d < DDIM; d++) s = fmaf(e[d], e[d], s);
        g_enorm[k] = s;
    }
}

// Kernel B: fused encodings-zeroing + argmin + z_st + one-hot scatter + loss partials
__global__ void __launch_bounds__(128, 2) vq_main(const float* __restrict__ z_e,
                                                  const float* __restrict__ emb,
                                                  float* __restrict__ out) {
    __shared__ float sE[TK * DDIM];
    __shared__ float sN[TK];
    __shared__ float sRed[4];

    const int tid = threadIdx.x;
    const int n   = blockIdx.x * 128 + tid;
    const int b   = n >> 10;
    const int hw  = n & 1023;

    // Zero this block's 128 one-hot rows (512 KB, coalesced STG.64.CS).
    // The encodings region is only 8-byte aligned (OFF_ENC*4 = 8 mod 16),
    // so float2 is the widest legal vector here (float4 traps: misaligned).
    // Streaming (.cs) stores: write-only, >L2-sized traffic — evict-first so
    // the emb tiles / z_e lines stay resident. Fire-and-forget: drains behind
    // the FMA mainloop, replacing a serial 134 MB memset kernel.
    {
        float2* encBase = (float2*)(out + (size_t)OFF_ENC)
                        + (size_t)blockIdx.x * (128 * KCODES / 2);
        const float2 z2 = make_float2(0.f, 0.f);
        #pragma unroll 8
        for (int i = 0; i < (128 * KCODES / 2) / 128; i++)
            __stcs(&encBase[tid + i * 128], z2);
    }

    // Load x (point vector): z_e[b][d][h][w], coalesced across lanes (hw contiguous)
    const float* xp = z_e + (size_t)b * (DDIM * HWSZ) + hw;
    float x[DDIM];
    #pragma unroll
    for (int d = 0; d < DDIM; d++) x[d] = xp[(size_t)d * HWSZ];

    // nx = ||x||^2, sequential in-order FMA
    float nx = 0.f;
    #pragma unroll
    for (int d = 0; d < DDIM; d++) nx = fmaf(x[d], x[d], nx);

    // Prescale by -2: fl((-2x)*e) == -2*fl(x*e) exactly, so the accumulated
    // value equals -fl(2*dot) with reference-identical rounding per step.
    #pragma unroll
    for (int d = 0; d < DDIM; d++) x[d] = -2.f * x[d];

    float best  = __int_as_float(0x7f800000);  // +inf
    int   bestk = 0;

    for (int kt = 0; kt < KCODES; kt += TK) {
        __syncthreads();
        // Stage TK code rows (row-major, d contiguous) into shared
        {
            const float4* src = (const float4*)(emb + (size_t)kt * DDIM);
            float4* dst = (float4*)sE;
            #pragma unroll
            for (int i = 0; i < (TK * DDIM / 4) / 128; i++)
                dst[tid + i * 128] = src[tid + i * 128];
            if (tid < TK) sN[tid] = g_enorm[kt + tid];
        }
        __syncthreads();

        #pragma unroll 1
        for (int kk = 0; kk < TK; kk += 4) {
            const float* e0 = &sE[(kk + 0) * DDIM];
            const float* e1 = &sE[(kk + 1) * DDIM];
            const float* e2 = &sE[(kk + 2) * DDIM];
            const float* e3 = &sE[(kk + 3) * DDIM];
            float a0 = 0.f, a1 = 0.f, a2 = 0.f, a3 = 0.f;
            // 4 independent sequential chains: rounding order per code matches
            // a plain in-order dot product; cross-code ILP hides FMA latency.
            #pragma unroll
            for (int d = 0; d < DDIM; d++) {
                a0 = fmaf(x[d], e0[d], a0);
                a1 = fmaf(x[d], e1[d], a1);
                a2 = fmaf(x[d], e2[d], a2);
                a3 = fmaf(x[d], e3[d], a3);
            }
            // dist = fl( fl(nx + ne_k) + (-2*dot) )  == reference association (A+B)-C
            float d0 = (nx + sN[kk + 0]) + a0;
            float d1 = (nx + sN[kk + 1]) + a1;
            float d2 = (nx + sN[kk + 2]) + a2;
            float d3 = (nx + sN[kk + 3]) + a3;
            if (d0 < best) { best = d0; bestk = kt + kk + 0; }
            if (d1 < best) { best = d1; bestk = kt + kk + 1; }
            if (d2 < best) { best = d2; bestk = kt + kk + 2; }
            if (d3 < best) { best = d3; bestk = kt + kk + 3; }
        }
    }

    g_idx[n] = bestk;

    // Epilogue: z_st = z + (z_q - z)  (bit-exact same op sequence as reference),
    // loss partial sum of (z_q - z)^2, encodings one-hot scatter.
    // The 1.0f store is ordered after this block's zero-stores by the
    // __syncthreads() barriers in the tile loop above.
    const float* eq = emb + (size_t)bestk * DDIM;
    float* zst = out + (size_t)b * (DDIM * HWSZ) + hw;
    float lsum = 0.f;
    #pragma unroll
    for (int d = 0; d < DDIM; d++) {
        float z  = -0.5f * x[d];        // exact recovery of original z
        float zq = eq[d];
        float t  = zq - z;
        __stcs(&zst[(size_t)d * HWSZ], z + t);   // write-only output, streaming
        lsum = fmaf(t, t, lsum);
    }
    __stcs(out + (size_t)OFF_ENC + (size_t)n * KCODES + bestk, 1.0f);

    // block reduce loss partial
    #pragma unroll
    for (int off = 16; off; off >>= 1)
        lsum += __shfl_down_sync(0xffffffffu, lsum, off);
    if ((tid & 31) == 0) sRed[tid >> 5] = lsum;
    __syncthreads();
    if (tid == 0)
        g_losspart[blockIdx.x] = (sRed[0] + sRed[1]) + (sRed[2] + sRed[3]);
}

// Kernel C: histogram -> perplexity, sum loss partials -> loss
__global__ void __launch_bounds__(1024) vq_final(float* __restrict__ out) {
    __shared__ int   hist[KCODES];
    __shared__ float red[KCODES];
    int t = threadIdx.x;
    hist[t] = 0;
    __syncthreads();
    #pragma unroll
    for (int i = 0; i < NPTS / KCODES; i++)
        atomicAdd(&hist[g_idx[t + i * KCODES]], 1);
    __syncthreads();

    float p = (float)hist[t] * (1.f / 32768.f);   // exact: divide by 2^15
    red[t] = p * logf(p + 1e-10f);
    __syncthreads();
    #pragma unroll
    for (int s = 512; s; s >>= 1) {
        if (t < s) red[t] += red[t + s];
        __syncthreads();
    }
    float S = red[0];
    __syncthreads();

    red[t] = (t < 256) ? g_losspart[t] : 0.f;
    __syncthreads();
    #pragma unroll
    for (int s = 512; s; s >>= 1) {
        if (t < s) red[t] += red[t + s];
        __syncthreads();
    }
    if (t == 0) {
        float m = red[0] * (1.f / 2097152.f);     // exact: divide by 2^21
        out[OFF_LOSS] = m + 0.25f * m;            // q_loss + 0.25*e_loss, same association
        out[OFF_PERP] = expf(-S);
    }
}

extern "C" void kernel_launch(void* const* d_in, const int* in_sizes, int n_in,
                              void* d_out, int out_size) {
    const float* z_e = (const float*)d_in[0];
    const float* emb = (const float*)d_in[1];
    float* out = (float*)d_out;

    vq_enorm<<<8, 128>>>(emb);
    vq_main<<<NPTS / 128, 128>>>(z_e, emb, out);
    vq_final<<<1, 1024>>>(out);
    (void)in_sizes; (void)n_in; (void)out_size;
}